// round 4
// baseline (speedup 1.0000x reference)
#include <cuda_runtime.h>

#define NPTS  16384
#define KNN_K 16

#define O_WB   0
#define O_W1A  4096
#define O_W2A  8192
#define O_W2B  12288
#define O_W3A  16384
#define O_W3B  20480
#define O_W3C  24576
#define O_F    28672
#define O_H1   32768
#define O_H2   36864
#define O_H3   40960
#define O_H4   45056
#define O_C    49152
#define SMEM_FLOATS 50176

__device__ __align__(16) int   g_knn[NPTS * KNN_K];
__device__ __align__(16) float g_const[NPTS * 256];

static __device__ __forceinline__ unsigned long long pack2(float a, float b) {
    unsigned long long r;
    asm("mov.b64 %0, {%1, %2};" : "=l"(r) : "f"(a), "f"(b));
    return r;
}
static __device__ __forceinline__ void unpack2(unsigned long long v, float &a, float &b) {
    asm("mov.b64 {%0, %1}, %2;" : "=f"(a), "=f"(b) : "l"(v));
}
static __device__ __forceinline__ void ffma2(unsigned long long &d, unsigned long long a, unsigned long long b) {
    asm("fma.rn.f32x2 %0, %1, %2, %0;" : "+l"(d) : "l"(a), "l"(b));
}

// ================= KNN: warp-per-query, atomic-free radix select =================
// per-warp scratch: keys16 u16[4096]@0 | l1 u8[64*32]@8192 | l2 u8[256*32]@10240 | bs/buf @18432 (1024B)
#define WSCR 19456
#define KNN_SMEM (65536 + 8 * WSCR)

__global__ void __launch_bounds__(256, 1) knn_kernel(const float* __restrict__ pos) {
    extern __shared__ char smraw[];
    float4* tile = (float4*)smraw;
    int t = threadIdx.x, w = t >> 5, lane = t & 31;
    char* wb = smraw + 65536 + w * WSCR;
    unsigned short*     keys16 = (unsigned short*)wb;
    unsigned char*      l1     = (unsigned char*)(wb + 8192);
    unsigned char*      l2     = (unsigned char*)(wb + 10240);
    unsigned*           bs     = (unsigned*)(wb + 18432);
    unsigned long long* buf    = (unsigned long long*)(wb + 18432);

    int b = blockIdx.x >> 6;
    int qoff = (blockIdx.x & 63) * 64;
    const float* P = pos + (size_t)(b << 12) * 3;
    for (int i = t; i < 4096; i += 256) {
        float px = P[3 * i], py = P[3 * i + 1], pz = P[3 * i + 2];
        tile[i] = make_float4(px, py, pz, px * px + py * py + pz * pz);
    }
    __syncthreads();

    for (int qi = 0; qi < 8; qi++) {
        int ql = qoff + w * 8 + qi;
        float4 qp = tile[ql];
        float qx = qp.x, qy = qp.y, qz = qp.z, qs = qp.w;

#pragma unroll
        for (int j = 0; j < 4; j++)  ((uint4*)l1)[lane + 32 * j] = make_uint4(0, 0, 0, 0);
#pragma unroll
        for (int j = 0; j < 16; j++) ((uint4*)l2)[lane + 32 * j] = make_uint4(0, 0, 0, 0);
        __syncwarp();

        // pass A: 16-bit key cache + level-1 (6-bit) lane-private histogram
#pragma unroll 4
        for (int i = 0; i < 128; i++) {
            int c = (i << 5) | lane;
            float4 pc = tile[c];
            float d2 = qs + pc.w - 2.0f * (qx * pc.x + qy * pc.y + qz * pc.z);
            unsigned kb = __float_as_uint(d2);
            kb ^= ((unsigned)((int)kb >> 31)) | 0x80000000u;
            keys16[c] = (unsigned short)(kb >> 16);
            l1[(kb >> 26) * 32 + lane]++;
        }
        __syncwarp();
        // reduce l1: word lane+32j holds 4 lane-counts of bin (4j + lane/8)
        {
            const unsigned* h32 = (const unsigned*)l1;
#pragma unroll
            for (int j = 0; j < 16; j++) {
                unsigned v = __dp4a(h32[lane + 32 * j], 0x01010101u, 0u);
                v += __shfl_xor_sync(~0u, v, 1);
                v += __shfl_xor_sync(~0u, v, 2);
                v += __shfl_xor_sync(~0u, v, 4);
                if ((lane & 7) == 0) bs[4 * j + (lane >> 3)] = v;
            }
        }
        __syncwarp();
        unsigned B1, cb1;
        {
            unsigned s0 = bs[lane * 2], s1 = bs[lane * 2 + 1];
            unsigned s = s0 + s1, pre = s;
#pragma unroll
            for (int o = 1; o < 32; o <<= 1) {
                unsigned v = __shfl_up_sync(~0u, pre, o);
                if (lane >= o) pre += v;
            }
            unsigned excl = pre - s;
            unsigned mb = __ballot_sync(~0u, (excl < 17u) && (pre >= 17u));
            int lead = __ffs(mb) - 1;
            unsigned Bv = 0, cv = 0;
            if (lane == lead) {
                if (excl + s0 >= 17u) { Bv = lane * 2;     cv = excl; }
                else                  { Bv = lane * 2 + 1; cv = excl + s0; }
            }
            B1 = __shfl_sync(~0u, Bv, lead);
            cb1 = __shfl_sync(~0u, cv, lead);
        }
        __syncwarp();

        // pass B: level-2 (8-bit) histogram within bin B1
#pragma unroll 4
        for (int i = 0; i < 128; i++) {
            int c = (i << 5) | lane;
            unsigned k16 = keys16[c];
            if ((k16 >> 10) == B1) l2[((k16 >> 2) & 255u) * 32 + lane]++;
        }
        __syncwarp();
        {
            const unsigned* g32 = (const unsigned*)l2;
#pragma unroll
            for (int j = 0; j < 64; j++) {
                unsigned v = __dp4a(g32[lane + 32 * j], 0x01010101u, 0u);
                v += __shfl_xor_sync(~0u, v, 1);
                v += __shfl_xor_sync(~0u, v, 2);
                v += __shfl_xor_sync(~0u, v, 4);
                if ((lane & 7) == 0) bs[4 * j + (lane >> 3)] = v;
            }
        }
        __syncwarp();
        unsigned cut;
        {
            unsigned target = 17u - cb1;
            unsigned t8[8], ssum = 0;
#pragma unroll
            for (int j = 0; j < 8; j++) { t8[j] = bs[lane * 8 + j]; ssum += t8[j]; }
            unsigned pre = ssum;
#pragma unroll
            for (int o = 1; o < 32; o <<= 1) {
                unsigned v = __shfl_up_sync(~0u, pre, o);
                if (lane >= o) pre += v;
            }
            unsigned excl = pre - ssum;
            unsigned mb = __ballot_sync(~0u, (excl < target) && (pre >= target));
            int lead = __ffs(mb) - 1;
            unsigned B2 = 0;
            if (lane == lead) {
                unsigned run = excl; bool done = false;
#pragma unroll
                for (int j = 0; j < 8; j++) {
                    if (!done && run + t8[j] >= target) { B2 = lane * 8 + j; done = true; }
                    run += t8[j];
                }
            }
            B2 = __shfl_sync(~0u, B2, lead);
            cut = (B1 << 8) | B2;
        }
        __syncwarp();

        // collect survivors (ballot compaction), recompute exact 32-bit key
        unsigned cnt = 0;
#pragma unroll 4
        for (int i = 0; i < 128; i++) {
            int c = (i << 5) | lane;
            bool pr = (unsigned)(keys16[c] >> 2) <= cut;
            unsigned bal = __ballot_sync(~0u, pr);
            if (pr) {
                unsigned p = cnt + __popc(bal & ((1u << lane) - 1u));
                if (p < 128u) {
                    float4 pc = tile[c];
                    float d2 = qs + pc.w - 2.0f * (qx * pc.x + qy * pc.y + qz * pc.z);
                    unsigned kb = __float_as_uint(d2);
                    kb ^= ((unsigned)((int)kb >> 31)) | 0x80000000u;
                    buf[p] = ((unsigned long long)kb << 32) | (unsigned)c;
                }
            }
            cnt += __popc(bal);
        }
        __syncwarp();

        // exact rank; drop rank 0 (self), keep 1..16
        int M = min(cnt, 128u);
        int qg = (b << 12) + ql;
        for (int si = lane; si < M; si += 32) {
            unsigned long long mv = buf[si];
            int r = 0;
            for (int j = 0; j < M; j++) r += (buf[j] < mv) ? 1 : 0;
            if (r >= 1 && r <= 16) g_knn[qg * KNN_K + (r - 1)] = (int)(mv & 0xFFFFFFFFu);
        }
        __syncwarp();
    }
}

// ================= per-point constants =================
__global__ void const_kernel(const float* __restrict__ x,
                             const float* __restrict__ Wf,  const float* __restrict__ bf,
                             const float* __restrict__ Wm1, const float* __restrict__ bm1,
                             const float* __restrict__ Wm2, const float* __restrict__ bm2,
                             const float* __restrict__ Wl,  const float* __restrict__ bl) {
    extern __shared__ float sm[];
    float* Wc   = sm;
    float* bias = sm + 64 * 256;
    float* xs   = bias + 256;
    int t = threadIdx.x;
    for (int i = t; i < 64 * 256; i += 256) {
        int d = i >> 8, j = i & 255;
        float v;
        if (j < 64)       v = Wf[d * 64 + j] - Wf[(128 + d) * 64 + j];
        else if (j < 128) v = Wm1[(64 + d) * 64 + (j - 64)];
        else if (j < 192) v = Wm2[(128 + d) * 64 + (j - 128)];
        else              v = Wl[(192 + d) * 64 + (j - 192)];
        Wc[i] = v;
    }
    bias[t] = (t < 64) ? bf[t] : (t < 128) ? bm1[t - 64] : (t < 192) ? bm2[t - 128] : bl[t - 192];

    for (int pt = blockIdx.x; pt < NPTS; pt += gridDim.x) {
        __syncthreads();
        if (t < 64) xs[t] = x[(size_t)pt * 64 + t];
        __syncthreads();
        float acc = bias[t];
#pragma unroll 8
        for (int d = 0; d < 64; d++) acc = fmaf(xs[d], Wc[d * 256 + t], acc);
        g_const[(size_t)pt * 256 + t] = acc;
    }
}

// ================= fused edge-MLP + max (unchanged from passing R2) =================
__global__ void __launch_bounds__(256, 1)
edge_mlp_kernel(const float* __restrict__ x,
                const float* __restrict__ Wf, const float* __restrict__ Wm1,
                const float* __restrict__ Wm2, const float* __restrict__ Wl,
                float* __restrict__ out) {
    extern __shared__ float sm[];
    int t = threadIdx.x;

    for (int i = t; i < 4096; i += 256) {
        int d = i >> 6, j = i & 63;
        sm[O_WB  + i] = Wf[(64 + d) * 64 + j] + Wf[(128 + d) * 64 + j];
        sm[O_W1A + i] = Wm1[i];
        sm[O_W2A + i] = Wm2[i];
        sm[O_W2B + i] = Wm2[4096 + i];
        sm[O_W3A + i] = Wl[i];
        sm[O_W3B + i] = Wl[4096 + i];
        sm[O_W3C + i] = Wl[8192 + i];
    }
    __syncthreads();

    const int k  = t >> 4;
    const int jb = (t & 15) << 2;
    unsigned long long a[4][2];

    for (int grp = blockIdx.x; grp < NPTS / 4; grp += gridDim.x) {
        int base = grp * 4;
        int b = base >> 12;
        {
            int r  = t >> 2;
            int q4 = t & 3;
            int nb = g_knn[grp * 64 + r];
            const float4* src = (const float4*)(x + ((size_t)(b << 12) + nb) * 64) + (q4 << 2);
            float4* dst = (float4*)(sm + O_F + (r << 6)) + (q4 << 2);
#pragma unroll
            for (int u = 0; u < 4; u++) dst[u] = src[u];
            ((float4*)(sm + O_C))[t] = ((const float4*)(g_const + (size_t)grp * 1024))[t];
        }
        __syncthreads();

        auto init_acc = [&](int coff) {
#pragma unroll
            for (int j = 0; j < 4; j++) {
                a[j][0] = pack2(sm[O_C +       coff + jb + j], sm[O_C + 256 + coff + jb + j]);
                a[j][1] = pack2(sm[O_C + 512 + coff + jb + j], sm[O_C + 768 + coff + jb + j]);
            }
        };
        auto accum = [&](int hoff, int woff) {
#pragma unroll 8
            for (int d = 0; d < 64; d++) {
                float4 w = *(const float4*)(sm + woff + (d << 6) + jb);
                ulonglong2 h2 = *(const ulonglong2*)(sm + hoff + (k << 8) + (d << 2));
                unsigned long long w0 = pack2(w.x, w.x), w1 = pack2(w.y, w.y);
                unsigned long long w2 = pack2(w.z, w.z), w3 = pack2(w.w, w.w);
                ffma2(a[0][0], h2.x, w0); ffma2(a[0][1], h2.y, w0);
                ffma2(a[1][0], h2.x, w1); ffma2(a[1][1], h2.y, w1);
                ffma2(a[2][0], h2.x, w2); ffma2(a[2][1], h2.y, w2);
                ffma2(a[3][0], h2.x, w3); ffma2(a[3][1], h2.y, w3);
            }
        };
        auto accum_f = [&](int woff) {
#pragma unroll 8
            for (int d = 0; d < 64; d++) {
                float4 w = *(const float4*)(sm + woff + (d << 6) + jb);
                float f0 = sm[O_F +        (k << 6) + d];
                float f1 = sm[O_F + 1024 + (k << 6) + d];
                float f2 = sm[O_F + 2048 + (k << 6) + d];
                float f3 = sm[O_F + 3072 + (k << 6) + d];
                unsigned long long hA = pack2(f0, f1), hB = pack2(f2, f3);
                unsigned long long w0 = pack2(w.x, w.x), w1 = pack2(w.y, w.y);
                unsigned long long w2 = pack2(w.z, w.z), w3 = pack2(w.w, w.w);
                ffma2(a[0][0], hA, w0); ffma2(a[0][1], hB, w0);
                ffma2(a[1][0], hA, w1); ffma2(a[1][1], hB, w1);
                ffma2(a[2][0], hA, w2); ffma2(a[2][1], hB, w2);
                ffma2(a[3][0], hA, w3); ffma2(a[3][1], hB, w3);
            }
        };
        auto store_h = [&](int hoff, bool relu) {
#pragma unroll
            for (int j = 0; j < 4; j++) {
                float v0, v1, v2, v3;
                unpack2(a[j][0], v0, v1); unpack2(a[j][1], v2, v3);
                if (relu) {
                    v0 = fmaxf(v0, 0.0f); v1 = fmaxf(v1, 0.0f);
                    v2 = fmaxf(v2, 0.0f); v3 = fmaxf(v3, 0.0f);
                }
                *(float4*)(sm + hoff + (k << 8) + ((jb + j) << 2)) = make_float4(v0, v1, v2, v3);
            }
        };

        init_acc(0);   accum_f(O_WB);                              store_h(O_H1, true);
        __syncwarp();
        init_acc(64);  accum(O_H1, O_W1A);                         store_h(O_H2, true);
        __syncwarp();
        init_acc(128); accum(O_H2, O_W2A); accum(O_H1, O_W2B);     store_h(O_H3, true);
        __syncwarp();
        init_acc(192); accum(O_H3, O_W3A); accum(O_H2, O_W3B); accum(O_H1, O_W3C);
        store_h(O_H4, false);
        __syncthreads();

        {
            int p = t & 3, j = t >> 2;
            int pt = base + p;
            size_t orow = (size_t)pt * 320;
            float m4 = -3.4e38f, m3 = -3.4e38f, m2 = -3.4e38f, m1 = -3.4e38f;
#pragma unroll
            for (int kk = 0; kk < 16; kk++) {
                int off = (kk << 8) + (j << 2) + p;
                m1 = fmaxf(m1, sm[O_H1 + off]);
                m2 = fmaxf(m2, sm[O_H2 + off]);
                m3 = fmaxf(m3, sm[O_H3 + off]);
                m4 = fmaxf(m4, sm[O_H4 + off]);
            }
            out[orow +       j] = m4;
            out[orow +  64 + j] = m3;
            out[orow + 128 + j] = m2;
            out[orow + 192 + j] = m1;
            out[orow + 256 + j] = x[(size_t)pt * 64 + j];
        }
        __syncthreads();
    }
}

extern "C" void kernel_launch(void* const* d_in, const int* in_sizes, int n_in,
                              void* d_out, int out_size) {
    const float* x   = (const float*)d_in[0];
    const float* pos = (const float*)d_in[1];
    const float* Wf  = (const float*)d_in[2];
    const float* bf  = (const float*)d_in[3];
    const float* Wm1 = (const float*)d_in[4];
    const float* bm1 = (const float*)d_in[5];
    const float* Wm2 = (const float*)d_in[6];
    const float* bm2 = (const float*)d_in[7];
    const float* Wl  = (const float*)d_in[8];
    const float* bl  = (const float*)d_in[9];
    float* out = (float*)d_out;

    cudaFuncSetAttribute(knn_kernel, cudaFuncAttributeMaxDynamicSharedMemorySize, KNN_SMEM);
    cudaFuncSetAttribute(const_kernel, cudaFuncAttributeMaxDynamicSharedMemorySize,
                         (64 * 256 + 256 + 64) * 4);
    cudaFuncSetAttribute(edge_mlp_kernel, cudaFuncAttributeMaxDynamicSharedMemorySize,
                         SMEM_FLOATS * 4);

    knn_kernel<<<256, 256, KNN_SMEM>>>(pos);
    const_kernel<<<256, 256, (64 * 256 + 256 + 64) * 4>>>(x, Wf, bf, Wm1, bm1, Wm2, bm2, Wl, bl);
    edge_mlp_kernel<<<148, 256, SMEM_FLOATS * 4>>>(x, Wf, Wm1, Wm2, Wl, out);
}

// round 5
// speedup vs baseline: 1.1320x; 1.1320x over previous
#include <cuda_runtime.h>

#define NPTS  16384
#define KNN_K 16

#define O_WB   0
#define O_W1A  4096
#define O_W2A  8192
#define O_W2B  12288
#define O_W3A  16384
#define O_W3B  20480
#define O_W3C  24576
#define O_F    28672
#define O_H1   32768
#define O_H2   36864
#define O_H3   40960
#define O_H4   45056
#define O_C    49152
#define SMEM_FLOATS 50176

__device__ __align__(16) int   g_knn[NPTS * KNN_K];
__device__ __align__(16) float g_const[NPTS * 256];

static __device__ __forceinline__ unsigned long long pack2(float a, float b) {
    unsigned long long r;
    asm("mov.b64 %0, {%1, %2};" : "=l"(r) : "f"(a), "f"(b));
    return r;
}
static __device__ __forceinline__ void unpack2(unsigned long long v, float &a, float &b) {
    asm("mov.b64 {%0, %1}, %2;" : "=f"(a), "=f"(b) : "l"(v));
}
static __device__ __forceinline__ void ffma2(unsigned long long &d, unsigned long long a, unsigned long long b) {
    asm("fma.rn.f32x2 %0, %1, %2, %0;" : "+l"(d) : "l"(a), "l"(b));
}

// find smallest digit with cum>=target over 256-bin u32 hist; lead lane writes outB/outCb
static __device__ __forceinline__ void warp_scan_find(const unsigned* __restrict__ h, unsigned target,
                                                      unsigned* outB, unsigned* outCb) {
    int lane = threadIdx.x & 31;
    unsigned loc[8], s = 0;
#pragma unroll
    for (int j = 0; j < 8; j++) { loc[j] = h[lane * 8 + j]; s += loc[j]; }
    unsigned pre = s;
#pragma unroll
    for (int o = 1; o < 32; o <<= 1) {
        unsigned v = __shfl_up_sync(0xffffffffu, pre, o);
        if (lane >= o) pre += v;
    }
    unsigned excl = pre - s;
    bool mine = (excl < target) && (excl + s >= target);
    unsigned mb = __ballot_sync(0xffffffffu, mine);
    int lead = __ffs(mb) - 1;
    if (lane == lead) {
        unsigned run = excl, B = 0, cbv = 0;
        bool done = false;
#pragma unroll
        for (int j = 0; j < 8; j++) {
            if (!done && run + loc[j] >= target) { B = lane * 8 + j; cbv = run; done = true; }
            run += loc[j];
        }
        *outB = B; *outCb = cbv;
    }
}

// ===== KNN: block radix select, 2 queries per barrier round, atomic-free hists =====
// smem: tile f4[4096]@0 | keys16 u16[2][4096]@65536 | whist u16[2][8][256]@81920
//       | red u32[2][256]@90112 | buf u64[2][128]@92160 | sv u32[2][6]@94208
#define KNN_SMEM 94352

__global__ void __launch_bounds__(256, 2) knn_kernel(const float* __restrict__ pos) {
    extern __shared__ char smraw[];
    float4*             tile   = (float4*)smraw;
    unsigned short*     keys16 = (unsigned short*)(smraw + 65536);
    unsigned short*     whist  = (unsigned short*)(smraw + 81920);
    unsigned*           red    = (unsigned*)(smraw + 90112);
    unsigned long long* buf    = (unsigned long long*)(smraw + 92160);
    unsigned*           sv     = (unsigned*)(smraw + 94208);

    int t = threadIdx.x, w = t >> 5, lane = t & 31;
    int b = blockIdx.x >> 6;
    int qoff = (blockIdx.x & 63) * 64;
    const float* P = pos + (size_t)(b << 12) * 3;
    for (int i = t; i < 4096; i += 256) {
        float px = P[3 * i], py = P[3 * i + 1], pz = P[3 * i + 2];
        tile[i] = make_float4(px, py, pz, px * px + py * py + pz * pz);
    }
    __syncthreads();

    for (int pair = 0; pair < 32; pair++) {
        int ql0 = qoff + pair * 2, ql1 = ql0 + 1;
        float4 q0 = tile[ql0], q1 = tile[ql1];

        // zero own warp's hist regions (warp-private -> no barrier needed)
        ((uint4*)whist)[      w * 32 + lane] = make_uint4(0, 0, 0, 0);
        ((uint4*)whist)[256 + w * 32 + lane] = make_uint4(0, 0, 0, 0);
        __syncwarp();

        // pass A: keys + level-1 hist (8-bit), both queries
#pragma unroll 4
        for (int i = 0; i < 16; i++) {
            int c = t + (i << 8);
            float4 pc = tile[c];
            float d20 = q0.w + pc.w - 2.0f * (q0.x * pc.x + q0.y * pc.y + q0.z * pc.z);
            float d21 = q1.w + pc.w - 2.0f * (q1.x * pc.x + q1.y * pc.y + q1.z * pc.z);
            unsigned k0 = __float_as_uint(d20); k0 ^= ((unsigned)((int)k0 >> 31)) | 0x80000000u;
            unsigned k1 = __float_as_uint(d21); k1 ^= ((unsigned)((int)k1 >> 31)) | 0x80000000u;
            keys16[c] = (unsigned short)(k0 >> 16);
            keys16[4096 + c] = (unsigned short)(k1 >> 16);
            unsigned bin0 = k0 >> 24;
            unsigned m0 = __match_any_sync(~0u, bin0);
            if (lane == __ffs(m0) - 1) whist[(w << 8) + bin0] += (unsigned short)__popc(m0);
            unsigned bin1 = k1 >> 24;
            unsigned m1 = __match_any_sync(~0u, bin1);
            if (lane == __ffs(m1) - 1) whist[2048 + (w << 8) + bin1] += (unsigned short)__popc(m1);
        }
        __syncthreads();
        {   // reduce 8 warp hists per query; thread t = bin t
            unsigned s0 = 0, s1 = 0;
#pragma unroll
            for (int wi = 0; wi < 8; wi++) {
                s0 += whist[(wi << 8) + t];
                s1 += whist[2048 + (wi << 8) + t];
            }
            red[t] = s0; red[256 + t] = s1;
        }
        __syncthreads();
        if (w < 2) warp_scan_find(red + (w << 8), 17u, &sv[w * 6 + 0], &sv[w * 6 + 1]);
        __syncthreads();

        // pass B: level-2 hist within bin B1
        ((uint4*)whist)[      w * 32 + lane] = make_uint4(0, 0, 0, 0);
        ((uint4*)whist)[256 + w * 32 + lane] = make_uint4(0, 0, 0, 0);
        __syncwarp();
        unsigned B10 = sv[0], B11 = sv[6];
#pragma unroll 4
        for (int i = 0; i < 16; i++) {
            int c = t + (i << 8);
            unsigned k0 = keys16[c];
            unsigned b20 = ((k0 >> 8) == B10) ? (k0 & 255u) : 0xffffffffu;
            unsigned m0 = __match_any_sync(~0u, b20);
            if (b20 != 0xffffffffu && lane == __ffs(m0) - 1) whist[(w << 8) + b20] += (unsigned short)__popc(m0);
            unsigned k1 = keys16[4096 + c];
            unsigned b21 = ((k1 >> 8) == B11) ? (k1 & 255u) : 0xffffffffu;
            unsigned m1 = __match_any_sync(~0u, b21);
            if (b21 != 0xffffffffu && lane == __ffs(m1) - 1) whist[2048 + (w << 8) + b21] += (unsigned short)__popc(m1);
        }
        __syncthreads();
        {
            unsigned s0 = 0, s1 = 0;
#pragma unroll
            for (int wi = 0; wi < 8; wi++) {
                s0 += whist[(wi << 8) + t];
                s1 += whist[2048 + (wi << 8) + t];
            }
            red[t] = s0; red[256 + t] = s1;
        }
        __syncthreads();
        if (w < 2) warp_scan_find(red + (w << 8), 17u - sv[w * 6 + 1], &sv[w * 6 + 2], &sv[w * 6 + 3]);
        if (t == 0) { sv[4] = 0; sv[10] = 0; }
        __syncthreads();

        // collect survivors (warp ballot + one counter atomic per chunk)
        unsigned cut0 = (sv[0] << 8) | sv[2];
        unsigned cut1 = (sv[6] << 8) | sv[8];
#pragma unroll 2
        for (int i = 0; i < 16; i++) {
            int c = t + (i << 8);
#pragma unroll
            for (int q = 0; q < 2; q++) {
                unsigned cut = q ? cut1 : cut0;
                float4 qq = q ? q1 : q0;
                bool pr = (unsigned)keys16[q * 4096 + c] <= cut;
                unsigned bal = __ballot_sync(~0u, pr);
                unsigned base = 0;
                if (lane == 0) base = atomicAdd(&sv[q * 6 + 4], (unsigned)__popc(bal));
                base = __shfl_sync(~0u, base, 0);
                if (pr) {
                    unsigned p = base + __popc(bal & ((1u << lane) - 1u));
                    if (p < 128u) {
                        float4 pc = tile[c];
                        float d2 = qq.w + pc.w - 2.0f * (qq.x * pc.x + qq.y * pc.y + qq.z * pc.z);
                        unsigned kb = __float_as_uint(d2);
                        kb ^= ((unsigned)((int)kb >> 31)) | 0x80000000u;
                        buf[q * 128 + p] = ((unsigned long long)kb << 32) | (unsigned)c;
                    }
                }
            }
        }
        __syncthreads();

        // exact rank (ties by index); rank 0 = self dropped
        {
            int q = t >> 7, si = t & 127;
            int M = min(sv[q * 6 + 4], 128u);
            if (si < M) {
                unsigned long long mv = buf[q * 128 + si];
                int r = 0;
                for (int j = 0; j < M; j++) r += (buf[q * 128 + j] < mv) ? 1 : 0;
                if (r >= 1 && r <= 16) {
                    int qg = (b << 12) + (q ? ql1 : ql0);
                    g_knn[qg * KNN_K + (r - 1)] = (int)(mv & 0xFFFFFFFFu);
                }
            }
        }
        __syncthreads();
    }
}

// ================= per-point constants =================
__global__ void const_kernel(const float* __restrict__ x,
                             const float* __restrict__ Wf,  const float* __restrict__ bf,
                             const float* __restrict__ Wm1, const float* __restrict__ bm1,
                             const float* __restrict__ Wm2, const float* __restrict__ bm2,
                             const float* __restrict__ Wl,  const float* __restrict__ bl) {
    extern __shared__ float sm[];
    float* Wc   = sm;
    float* bias = sm + 64 * 256;
    float* xs   = bias + 256;
    int t = threadIdx.x;
    for (int i = t; i < 64 * 256; i += 256) {
        int d = i >> 8, j = i & 255;
        float v;
        if (j < 64)       v = Wf[d * 64 + j] - Wf[(128 + d) * 64 + j];
        else if (j < 128) v = Wm1[(64 + d) * 64 + (j - 64)];
        else if (j < 192) v = Wm2[(128 + d) * 64 + (j - 128)];
        else              v = Wl[(192 + d) * 64 + (j - 192)];
        Wc[i] = v;
    }
    bias[t] = (t < 64) ? bf[t] : (t < 128) ? bm1[t - 64] : (t < 192) ? bm2[t - 128] : bl[t - 192];

    for (int pt = blockIdx.x; pt < NPTS; pt += gridDim.x) {
        __syncthreads();
        if (t < 64) xs[t] = x[(size_t)pt * 64 + t];
        __syncthreads();
        float acc = bias[t];
#pragma unroll 8
        for (int d = 0; d < 64; d++) acc = fmaf(xs[d], Wc[d * 256 + t], acc);
        g_const[(size_t)pt * 256 + t] = acc;
    }
}

// ================= fused edge-MLP + max (unchanged, proven) =================
__global__ void __launch_bounds__(256, 1)
edge_mlp_kernel(const float* __restrict__ x,
                const float* __restrict__ Wf, const float* __restrict__ Wm1,
                const float* __restrict__ Wm2, const float* __restrict__ Wl,
                float* __restrict__ out) {
    extern __shared__ float sm[];
    int t = threadIdx.x;

    for (int i = t; i < 4096; i += 256) {
        int d = i >> 6, j = i & 63;
        sm[O_WB  + i] = Wf[(64 + d) * 64 + j] + Wf[(128 + d) * 64 + j];
        sm[O_W1A + i] = Wm1[i];
        sm[O_W2A + i] = Wm2[i];
        sm[O_W2B + i] = Wm2[4096 + i];
        sm[O_W3A + i] = Wl[i];
        sm[O_W3B + i] = Wl[4096 + i];
        sm[O_W3C + i] = Wl[8192 + i];
    }
    __syncthreads();

    const int k  = t >> 4;
    const int jb = (t & 15) << 2;
    unsigned long long a[4][2];

    for (int grp = blockIdx.x; grp < NPTS / 4; grp += gridDim.x) {
        int base = grp * 4;
        int b = base >> 12;
        {
            int r  = t >> 2;
            int q4 = t & 3;
            int nb = g_knn[grp * 64 + r];
            const float4* src = (const float4*)(x + ((size_t)(b << 12) + nb) * 64) + (q4 << 2);
            float4* dst = (float4*)(sm + O_F + (r << 6)) + (q4 << 2);
#pragma unroll
            for (int u = 0; u < 4; u++) dst[u] = src[u];
            ((float4*)(sm + O_C))[t] = ((const float4*)(g_const + (size_t)grp * 1024))[t];
        }
        __syncthreads();

        auto init_acc = [&](int coff) {
#pragma unroll
            for (int j = 0; j < 4; j++) {
                a[j][0] = pack2(sm[O_C +       coff + jb + j], sm[O_C + 256 + coff + jb + j]);
                a[j][1] = pack2(sm[O_C + 512 + coff + jb + j], sm[O_C + 768 + coff + jb + j]);
            }
        };
        auto accum = [&](int hoff, int woff) {
#pragma unroll 8
            for (int d = 0; d < 64; d++) {
                float4 w = *(const float4*)(sm + woff + (d << 6) + jb);
                ulonglong2 h2 = *(const ulonglong2*)(sm + hoff + (k << 8) + (d << 2));
                unsigned long long w0 = pack2(w.x, w.x), w1 = pack2(w.y, w.y);
                unsigned long long w2 = pack2(w.z, w.z), w3 = pack2(w.w, w.w);
                ffma2(a[0][0], h2.x, w0); ffma2(a[0][1], h2.y, w0);
                ffma2(a[1][0], h2.x, w1); ffma2(a[1][1], h2.y, w1);
                ffma2(a[2][0], h2.x, w2); ffma2(a[2][1], h2.y, w2);
                ffma2(a[3][0], h2.x, w3); ffma2(a[3][1], h2.y, w3);
            }
        };
        auto accum_f = [&](int woff) {
#pragma unroll 8
            for (int d = 0; d < 64; d++) {
                float4 w = *(const float4*)(sm + woff + (d << 6) + jb);
                float f0 = sm[O_F +        (k << 6) + d];
                float f1 = sm[O_F + 1024 + (k << 6) + d];
                float f2 = sm[O_F + 2048 + (k << 6) + d];
                float f3 = sm[O_F + 3072 + (k << 6) + d];
                unsigned long long hA = pack2(f0, f1), hB = pack2(f2, f3);
                unsigned long long w0 = pack2(w.x, w.x), w1 = pack2(w.y, w.y);
                unsigned long long w2 = pack2(w.z, w.z), w3 = pack2(w.w, w.w);
                ffma2(a[0][0], hA, w0); ffma2(a[0][1], hB, w0);
                ffma2(a[1][0], hA, w1); ffma2(a[1][1], hB, w1);
                ffma2(a[2][0], hA, w2); ffma2(a[2][1], hB, w2);
                ffma2(a[3][0], hA, w3); ffma2(a[3][1], hB, w3);
            }
        };
        auto store_h = [&](int hoff, bool relu) {
#pragma unroll
            for (int j = 0; j < 4; j++) {
                float v0, v1, v2, v3;
                unpack2(a[j][0], v0, v1); unpack2(a[j][1], v2, v3);
                if (relu) {
                    v0 = fmaxf(v0, 0.0f); v1 = fmaxf(v1, 0.0f);
                    v2 = fmaxf(v2, 0.0f); v3 = fmaxf(v3, 0.0f);
                }
                *(float4*)(sm + hoff + (k << 8) + ((jb + j) << 2)) = make_float4(v0, v1, v2, v3);
            }
        };

        init_acc(0);   accum_f(O_WB);                              store_h(O_H1, true);
        __syncwarp();
        init_acc(64);  accum(O_H1, O_W1A);                         store_h(O_H2, true);
        __syncwarp();
        init_acc(128); accum(O_H2, O_W2A); accum(O_H1, O_W2B);     store_h(O_H3, true);
        __syncwarp();
        init_acc(192); accum(O_H3, O_W3A); accum(O_H2, O_W3B); accum(O_H1, O_W3C);
        store_h(O_H4, false);
        __syncthreads();

        {
            int p = t & 3, j = t >> 2;
            int pt = base + p;
            size_t orow = (size_t)pt * 320;
            float m4 = -3.4e38f, m3 = -3.4e38f, m2 = -3.4e38f, m1 = -3.4e38f;
#pragma unroll
            for (int kk = 0; kk < 16; kk++) {
                int off = (kk << 8) + (j << 2) + p;
                m1 = fmaxf(m1, sm[O_H1 + off]);
                m2 = fmaxf(m2, sm[O_H2 + off]);
                m3 = fmaxf(m3, sm[O_H3 + off]);
                m4 = fmaxf(m4, sm[O_H4 + off]);
            }
            out[orow +       j] = m4;
            out[orow +  64 + j] = m3;
            out[orow + 128 + j] = m2;
            out[orow + 192 + j] = m1;
            out[orow + 256 + j] = x[(size_t)pt * 64 + j];
        }
        __syncthreads();
    }
}

extern "C" void kernel_launch(void* const* d_in, const int* in_sizes, int n_in,
                              void* d_out, int out_size) {
    const float* x   = (const float*)d_in[0];
    const float* pos = (const float*)d_in[1];
    const float* Wf  = (const float*)d_in[2];
    const float* bf  = (const float*)d_in[3];
    const float* Wm1 = (const float*)d_in[4];
    const float* bm1 = (const float*)d_in[5];
    const float* Wm2 = (const float*)d_in[6];
    const float* bm2 = (const float*)d_in[7];
    const float* Wl  = (const float*)d_in[8];
    const float* bl  = (const float*)d_in[9];
    float* out = (float*)d_out;

    cudaFuncSetAttribute(knn_kernel, cudaFuncAttributeMaxDynamicSharedMemorySize, KNN_SMEM);
    cudaFuncSetAttribute(const_kernel, cudaFuncAttributeMaxDynamicSharedMemorySize,
                         (64 * 256 + 256 + 64) * 4);
    cudaFuncSetAttribute(edge_mlp_kernel, cudaFuncAttributeMaxDynamicSharedMemorySize,
                         SMEM_FLOATS * 4);

    knn_kernel<<<256, 256, KNN_SMEM>>>(pos);
    const_kernel<<<256, 256, (64 * 256 + 256 + 64) * 4>>>(x, Wf, bf, Wm1, bm1, Wm2, bm2, Wl, bl);
    edge_mlp_kernel<<<148, 256, SMEM_FLOATS * 4>>>(x, Wf, Wm1, Wm2, Wl, out);
}

// round 8
// speedup vs baseline: 1.2369x; 1.0927x over previous
#include <cuda_runtime.h>

#define NPTS  16384
#define KNN_K 16
#define QB    64

// edge_mlp smem offsets (weights swizzled-transposed, pitch 64)
#define O_WB   0
#define O_W1A  4096
#define O_W2A  8192
#define O_W2B  12288
#define O_W3A  16384
#define O_W3B  20480
#define O_W3C  24576
#define O_F    28672
#define O_H1   32768
#define O_H2   36864
#define O_H3   40960
#define O_H4   45056
#define O_C    49152
#define SMEM_FLOATS 50176

__device__ __align__(16) int   g_knn[NPTS * KNN_K];
__device__ __align__(16) float g_const[NPTS * 256];

static __device__ __forceinline__ unsigned long long pack2(float a, float b) {
    unsigned long long r;
    asm("mov.b64 %0, {%1, %2};" : "=l"(r) : "f"(a), "f"(b));
    return r;
}
static __device__ __forceinline__ void unpack2(unsigned long long v, float &a, float &b) {
    asm("mov.b64 {%0, %1}, %2;" : "=f"(a), "=f"(b) : "l"(v));
}
static __device__ __forceinline__ void ffma2(unsigned long long &d, unsigned long long a, unsigned long long b) {
    asm("fma.rn.f32x2 %0, %1, %2, %0;" : "+l"(d) : "l"(a), "l"(b));
}

// ================= KNN (round-2 proven version, verbatim) =================
static __device__ __forceinline__ void warp_scan_find(const unsigned* __restrict__ h, unsigned target,
                                                      unsigned* outB, unsigned* outCb) {
    int lane = threadIdx.x & 31;
    unsigned loc[8], s = 0;
#pragma unroll
    for (int j = 0; j < 8; j++) { loc[j] = h[lane * 8 + j]; s += loc[j]; }
    unsigned pre = s;
#pragma unroll
    for (int o = 1; o < 32; o <<= 1) {
        unsigned v = __shfl_up_sync(0xffffffffu, pre, o);
        if (lane >= o) pre += v;
    }
    unsigned excl = pre - s;
    bool mine = (excl < target) && (excl + s >= target);
    unsigned mb = __ballot_sync(0xffffffffu, mine);
    int lead = __ffs(mb) - 1;
    if (lane == lead) {
        unsigned run = excl, B = 0, cbv = 0;
        bool done = false;
#pragma unroll
        for (int j = 0; j < 8; j++) {
            if (!done && run + loc[j] >= target) { B = lane * 8 + j; cbv = run; done = true; }
            run += loc[j];
        }
        *outB = B; *outCb = cbv;
    }
}

__global__ void __launch_bounds__(256, 2) knn_kernel(const float* __restrict__ pos) {
    extern __shared__ char smraw[];
    float4*   tile  = (float4*)smraw;
    unsigned* keys  = (unsigned*)(smraw + 65536);
    unsigned* hist  = (unsigned*)(smraw + 81920);
    unsigned* hist2 = (unsigned*)(smraw + 82944);
    unsigned* bufK  = (unsigned*)(smraw + 83968);
    int*      bufI  = (int*)(smraw + 84480);
    unsigned* sv    = (unsigned*)(smraw + 84992);

    int t = threadIdx.x;
    int lane = t & 31;
    int b = blockIdx.x >> 6;
    int qoff = (blockIdx.x & 63) * QB;
    const float* P = pos + ((size_t)(b << 12)) * 3;
    for (int i = t; i < 4096; i += 256) {
        float px = P[3 * i], py = P[3 * i + 1], pz = P[3 * i + 2];
        tile[i] = make_float4(px, py, pz, px * px + py * py + pz * pz);
    }
    __syncthreads();

    for (int qi = 0; qi < QB; qi++) {
        int ql = qoff + qi;
        float4 qp = tile[ql];
        float qx = qp.x, qy = qp.y, qz = qp.z, qs = qp.w;
        hist[t] = 0; hist2[t] = 0;
        if (t == 0) sv[3] = 0;
        __syncthreads();

#pragma unroll 4
        for (int i = 0; i < 16; i++) {
            int c = t + (i << 8);
            float4 pc = tile[c];
            float d2 = qs + pc.w - 2.0f * (qx * pc.x + qy * pc.y + qz * pc.z);
            unsigned kb = __float_as_uint(d2);
            kb ^= ((unsigned)((int)kb >> 31)) | 0x80000000u;
            keys[c] = kb;
            unsigned bin = kb >> 24;
            unsigned m = __match_any_sync(0xffffffffu, bin);
            if (lane == __ffs(m) - 1) atomicAdd(&hist[bin], (unsigned)__popc(m));
        }
        __syncthreads();
        if (t < 32) warp_scan_find(hist, 17u, sv + 0, sv + 1);
        __syncthreads();
        unsigned B = sv[0], cb = sv[1];

#pragma unroll 4
        for (int i = 0; i < 16; i++) {
            int c = t + (i << 8);
            unsigned key = keys[c];
            unsigned b2 = ((key >> 24) == B) ? ((key >> 16) & 255u) : 0xffffffffu;
            unsigned m = __match_any_sync(0xffffffffu, b2);
            if (b2 != 0xffffffffu && lane == __ffs(m) - 1) atomicAdd(&hist2[b2], (unsigned)__popc(m));
        }
        __syncthreads();
        if (t < 32) warp_scan_find(hist2, 17u - cb, sv + 2, sv + 1);
        __syncthreads();
        unsigned cut = (B << 8) | sv[2];

#pragma unroll 4
        for (int i = 0; i < 16; i++) {
            int c = t + (i << 8);
            unsigned key = keys[c];
            if ((key >> 16) <= cut) {
                unsigned p = atomicAdd(&sv[3], 1u);
                if (p < 128u) { bufK[p] = key; bufI[p] = c; }
            }
        }
        __syncthreads();

        int M = min(sv[3], 128u);
        if (t < M) {
            unsigned mk = bufK[t]; int mi = bufI[t];
            int r = 0;
            for (int j = 0; j < M; j++) {
                unsigned ok = bufK[j]; int oi = bufI[j];
                if (ok < mk || (ok == mk && oi < mi)) r++;
            }
            if (r >= 1 && r <= 16) {
                int qg = (b << 12) + ql;
                g_knn[qg * KNN_K + (r - 1)] = mi;
            }
        }
        __syncthreads();
    }
}

// ================= per-point constants =================
__global__ void const_kernel(const float* __restrict__ x,
                             const float* __restrict__ Wf,  const float* __restrict__ bf,
                             const float* __restrict__ Wm1, const float* __restrict__ bm1,
                             const float* __restrict__ Wm2, const float* __restrict__ bm2,
                             const float* __restrict__ Wl,  const float* __restrict__ bl) {
    extern __shared__ float sm[];
    float* Wc   = sm;
    float* bias = sm + 64 * 256;
    float* xs   = bias + 256;
    int t = threadIdx.x;
    for (int i = t; i < 64 * 256; i += 256) {
        int d = i >> 8, j = i & 255;
        float v;
        if (j < 64)       v = Wf[d * 64 + j] - Wf[(128 + d) * 64 + j];
        else if (j < 128) v = Wm1[(64 + d) * 64 + (j - 64)];
        else if (j < 192) v = Wm2[(128 + d) * 64 + (j - 128)];
        else              v = Wl[(192 + d) * 64 + (j - 192)];
        Wc[i] = v;
    }
    bias[t] = (t < 64) ? bf[t] : (t < 128) ? bm1[t - 64] : (t < 192) ? bm2[t - 128] : bl[t - 192];

    for (int pt = blockIdx.x; pt < NPTS; pt += gridDim.x) {
        __syncthreads();
        if (t < 64) xs[t] = x[(size_t)pt * 64 + t];
        __syncthreads();
        float acc = bias[t];
#pragma unroll 8
        for (int d = 0; d < 64; d++) acc = fmaf(xs[d], Wc[d * 256 + t], acc);
        g_const[(size_t)pt * 256 + t] = acc;
    }
}

// ===== fused edge-MLP + max: even/odd f32x2 pairing, swizzled transposed weights =====
// weight element (j,d) stored at: woff + j*64 + (((d>>2) ^ ((j>>2)&7))<<2) + (d&3)
// load: w at ds=sw(d4) (contents = W[d4..d4+3], since sw is an involution); h at plain d4.
__global__ void __launch_bounds__(256, 1)
edge_mlp_kernel(const float* __restrict__ x,
                const float* __restrict__ Wf, const float* __restrict__ Wm1,
                const float* __restrict__ Wm2, const float* __restrict__ Wl,
                float* __restrict__ out) {
    extern __shared__ float sm[];
    int t = threadIdx.x;

    for (int i = t; i < 4096; i += 256) {
        int d = i >> 6, j = i & 63;
        int o = j * 64 + ((((d >> 2) ^ ((j >> 2) & 7))) << 2) + (d & 3);
        sm[O_WB  + o] = Wf[(64 + d) * 64 + j] + Wf[(128 + d) * 64 + j];
        sm[O_W1A + o] = Wm1[i];
        sm[O_W2A + o] = Wm2[i];
        sm[O_W2B + o] = Wm2[4096 + i];
        sm[O_W3A + o] = Wl[i];
        sm[O_W3B + o] = Wl[4096 + i];
        sm[O_W3C + o] = Wl[8192 + i];
    }
    __syncthreads();

    const int k   = t >> 4;          // neighbor 0..15
    const int jb  = (t & 15) << 2;   // output column base
    const int key = (jb >> 2) & 7;   // swizzle key (same for the thread's 4 columns)
    unsigned long long a[4][4];      // [p][j] = (even-d sum, odd-d sum)

    for (int grp = blockIdx.x; grp < NPTS / 4; grp += gridDim.x) {
        int base = grp * 4;
        int b = base >> 12;
        {   // gather knn feats [p][k][64] + constants
            int r  = t >> 2;
            int q4 = t & 3;
            int nb = g_knn[grp * 64 + r];
            const float4* src = (const float4*)(x + ((size_t)(b << 12) + nb) * 64) + (q4 << 2);
            float4* dst = (float4*)(sm + O_F + (r << 6)) + (q4 << 2);
#pragma unroll
            for (int u = 0; u < 4; u++) dst[u] = src[u];
            ((float4*)(sm + O_C))[t] = ((const float4*)(g_const + (size_t)grp * 1024))[t];
        }
        __syncthreads();

        auto init_acc = [&](int coff) {
#pragma unroll
            for (int p = 0; p < 4; p++)
#pragma unroll
                for (int j = 0; j < 4; j++)
                    a[p][j] = pack2(sm[O_C + (p << 8) + coff + jb + j], 0.0f);
        };
        // h layout [k][p][64]; w at swizzled ds, h at plain d4
        auto accum = [&](int hoff, int woff) {
            const float* hb = sm + hoff + (k << 8);
            const float* wp = sm + woff + (jb << 6);
#pragma unroll
            for (int d4 = 0; d4 < 64; d4 += 4) {
                int ds = (((d4 >> 2) ^ key) << 2);
                ulonglong2 w0 = *(const ulonglong2*)(wp +       ds);
                ulonglong2 w1 = *(const ulonglong2*)(wp +  64 + ds);
                ulonglong2 w2 = *(const ulonglong2*)(wp + 128 + ds);
                ulonglong2 w3 = *(const ulonglong2*)(wp + 192 + ds);
                ulonglong2 h0 = *(const ulonglong2*)(hb +       d4);
                ulonglong2 h1 = *(const ulonglong2*)(hb +  64 + d4);
                ulonglong2 h2 = *(const ulonglong2*)(hb + 128 + d4);
                ulonglong2 h3 = *(const ulonglong2*)(hb + 192 + d4);
                ffma2(a[0][0], h0.x, w0.x); ffma2(a[0][1], h0.x, w1.x); ffma2(a[0][2], h0.x, w2.x); ffma2(a[0][3], h0.x, w3.x);
                ffma2(a[1][0], h1.x, w0.x); ffma2(a[1][1], h1.x, w1.x); ffma2(a[1][2], h1.x, w2.x); ffma2(a[1][3], h1.x, w3.x);
                ffma2(a[2][0], h2.x, w0.x); ffma2(a[2][1], h2.x, w1.x); ffma2(a[2][2], h2.x, w2.x); ffma2(a[2][3], h2.x, w3.x);
                ffma2(a[3][0], h3.x, w0.x); ffma2(a[3][1], h3.x, w1.x); ffma2(a[3][2], h3.x, w2.x); ffma2(a[3][3], h3.x, w3.x);
                ffma2(a[0][0], h0.y, w0.y); ffma2(a[0][1], h0.y, w1.y); ffma2(a[0][2], h0.y, w2.y); ffma2(a[0][3], h0.y, w3.y);
                ffma2(a[1][0], h1.y, w0.y); ffma2(a[1][1], h1.y, w1.y); ffma2(a[1][2], h1.y, w2.y); ffma2(a[1][3], h1.y, w3.y);
                ffma2(a[2][0], h2.y, w0.y); ffma2(a[2][1], h2.y, w1.y); ffma2(a[2][2], h2.y, w2.y); ffma2(a[2][3], h2.y, w3.y);
                ffma2(a[3][0], h3.y, w0.y); ffma2(a[3][1], h3.y, w1.y); ffma2(a[3][2], h3.y, w2.y); ffma2(a[3][3], h3.y, w3.y);
            }
        };
        // layer-1 input F is [p][k][64]
        auto accum_f = [&](int woff) {
            const float* f0 = sm + O_F + (k << 6);
            const float* wp = sm + woff + (jb << 6);
#pragma unroll
            for (int d4 = 0; d4 < 64; d4 += 4) {
                int ds = (((d4 >> 2) ^ key) << 2);
                ulonglong2 w0 = *(const ulonglong2*)(wp +       ds);
                ulonglong2 w1 = *(const ulonglong2*)(wp +  64 + ds);
                ulonglong2 w2 = *(const ulonglong2*)(wp + 128 + ds);
                ulonglong2 w3 = *(const ulonglong2*)(wp + 192 + ds);
                ulonglong2 h0 = *(const ulonglong2*)(f0 +        d4);
                ulonglong2 h1 = *(const ulonglong2*)(f0 + 1024 + d4);
                ulonglong2 h2 = *(const ulonglong2*)(f0 + 2048 + d4);
                ulonglong2 h3 = *(const ulonglong2*)(f0 + 3072 + d4);
                ffma2(a[0][0], h0.x, w0.x); ffma2(a[0][1], h0.x, w1.x); ffma2(a[0][2], h0.x, w2.x); ffma2(a[0][3], h0.x, w3.x);
                ffma2(a[1][0], h1.x, w0.x); ffma2(a[1][1], h1.x, w1.x); ffma2(a[1][2], h1.x, w2.x); ffma2(a[1][3], h1.x, w3.x);
                ffma2(a[2][0], h2.x, w0.x); ffma2(a[2][1], h2.x, w1.x); ffma2(a[2][2], h2.x, w2.x); ffma2(a[2][3], h2.x, w3.x);
                ffma2(a[3][0], h3.x, w0.x); ffma2(a[3][1], h3.x, w1.x); ffma2(a[3][2], h3.x, w2.x); ffma2(a[3][3], h3.x, w3.x);
                ffma2(a[0][0], h0.y, w0.y); ffma2(a[0][1], h0.y, w1.y); ffma2(a[0][2], h0.y, w2.y); ffma2(a[0][3], h0.y, w3.y);
                ffma2(a[1][0], h1.y, w0.y); ffma2(a[1][1], h1.y, w1.y); ffma2(a[1][2], h1.y, w2.y); ffma2(a[1][3], h1.y, w3.y);
                ffma2(a[2][0], h2.y, w0.y); ffma2(a[2][1], h2.y, w1.y); ffma2(a[2][2], h2.y, w2.y); ffma2(a[2][3], h2.y, w3.y);
                ffma2(a[3][0], h3.y, w0.y); ffma2(a[3][1], h3.y, w1.y); ffma2(a[3][2], h3.y, w2.y); ffma2(a[3][3], h3.y, w3.y);
            }
        };
        auto store_h = [&](int hoff, bool relu) {
            float* hb = sm + hoff + (k << 8);
#pragma unroll
            for (int p = 0; p < 4; p++) {
                float v[4];
#pragma unroll
                for (int j = 0; j < 4; j++) {
                    float e, o;
                    unpack2(a[p][j], e, o);
                    v[j] = e + o;
                    if (relu) v[j] = fmaxf(v[j], 0.0f);
                }
                *(float4*)(hb + (p << 6) + jb) = make_float4(v[0], v[1], v[2], v[3]);
            }
        };

        init_acc(0);   accum_f(O_WB);                              store_h(O_H1, true);
        __syncwarp();
        init_acc(64);  accum(O_H1, O_W1A);                         store_h(O_H2, true);
        __syncwarp();
        init_acc(128); accum(O_H2, O_W2A); accum(O_H1, O_W2B);     store_h(O_H3, true);
        __syncwarp();
        init_acc(192); accum(O_H3, O_W3A); accum(O_H2, O_W3B); accum(O_H1, O_W3C);
        store_h(O_H4, false);
        __syncthreads();

        {   // max over K; h layout [k][p][64]
            int p = t >> 6, j = t & 63;
            int pt = base + p;
            size_t orow = (size_t)pt * 320;
            float m4 = -3.4e38f, m3 = -3.4e38f, m2 = -3.4e38f, m1 = -3.4e38f;
#pragma unroll
            for (int kk = 0; kk < 16; kk++) {
                int off = (kk << 8) + (p << 6) + j;
                m1 = fmaxf(m1, sm[O_H1 + off]);
                m2 = fmaxf(m2, sm[O_H2 + off]);
                m3 = fmaxf(m3, sm[O_H3 + off]);
                m4 = fmaxf(m4, sm[O_H4 + off]);
            }
            out[orow +       j] = m4;
            out[orow +  64 + j] = m3;
            out[orow + 128 + j] = m2;
            out[orow + 192 + j] = m1;
            out[orow + 256 + j] = x[(size_t)pt * 64 + j];
        }
        __syncthreads();
    }
}

extern "C" void kernel_launch(void* const* d_in, const int* in_sizes, int n_in,
                              void* d_out, int out_size) {
    const float* x   = (const float*)d_in[0];
    const float* pos = (const float*)d_in[1];
    const float* Wf  = (const float*)d_in[2];
    const float* bf  = (const float*)d_in[3];
    const float* Wm1 = (const float*)d_in[4];
    const float* bm1 = (const float*)d_in[5];
    const float* Wm2 = (const float*)d_in[6];
    const float* bm2 = (const float*)d_in[7];
    const float* Wl  = (const float*)d_in[8];
    const float* bl  = (const float*)d_in[9];
    float* out = (float*)d_out;

    cudaFuncSetAttribute(knn_kernel, cudaFuncAttributeMaxDynamicSharedMemorySize, 85248);
    cudaFuncSetAttribute(const_kernel, cudaFuncAttributeMaxDynamicSharedMemorySize,
                         (64 * 256 + 256 + 64) * 4);
    cudaFuncSetAttribute(edge_mlp_kernel, cudaFuncAttributeMaxDynamicSharedMemorySize,
                         SMEM_FLOATS * 4);

    knn_kernel<<<256, 256, 85248>>>(pos);
    const_kernel<<<256, 256, (64 * 256 + 256 + 64) * 4>>>(x, Wf, bf, Wm1, bm1, Wm2, bm2, Wl, bl);
    edge_mlp_kernel<<<148, 256, SMEM_FLOATS * 4>>>(x, Wf, Wm1, Wm2, Wl, out);
}